// round 16
// baseline (speedup 1.0000x reference)
#include <cuda_runtime.h>
#include <cooperative_groups.h>
namespace cg = cooperative_groups;

#define B 64
#define NEG_BIG (-3.402823466e38f)

// ---------------- scratch (device globals; no allocation) ----------------
__device__ float g_t1[B * 128 * 128];
__device__ float g_t6[B * 256];                       // LN6-applied FC input
__device__ __align__(16) float g_fcp[4][B * 1024];    // FC partials (k-split 4)
__device__ __align__(16) float g_wT[225536];          // transposed L2..L6 weights
__device__ __align__(16) float g_w1T[16384 * 49];     // transposed L1 weights
__device__ float g_sink;

// wT segment bases (floats)
#define WT2 0
#define WT3 102400
#define WT4 204800
#define WT5 214016
#define WT6 223232
#define WT_TOTAL 225536

#define W1N 16384

// prep grid sections
#define PB_W1   128
#define PB_W2   32
#define PB_W3   32
#define PB_SC   81
#define PB_FCW  1024
#define PB_TOTAL (PB_W1 + PB_W2 + PB_W3 + PB_SC + PB_FCW)   // 1297

// =====================================================================
// prep: tiled transposes (coalesced both sides) + scalar small + prewarm
// =====================================================================
template <int KB>
__device__ __forceinline__ void transpose_tile(
    const float* __restrict__ src, float* __restrict__ dst,
    int NPOS, int p0, float* sm)
{
    constexpr int G4 = (KB / 4) * 4;
    const int tid = threadIdx.x;
    for (int i = tid; i < 128 * KB; i += 256)
        sm[i] = src[p0 * KB + i];
    __syncthreads();
    for (int idx = tid; idx < 128 * G4; idx += 256) {
        int g = idx >> 9;
        int r = idx & 511;
        int lp = r >> 2, j = r & 3;
        dst[g * 4 * NPOS + (p0 + lp) * 4 + j] = sm[lp * KB + 4 * g + j];
    }
    if (tid < 128)
        dst[G4 * NPOS + p0 + tid] = sm[tid * KB + G4];
}

__global__ __launch_bounds__(256) void prep_kernel(
    const float* __restrict__ w1,
    const float* __restrict__ w2, const float* __restrict__ w3,
    const float* __restrict__ w4, const float* __restrict__ w5,
    const float* __restrict__ w6, const float* __restrict__ fcw)
{
    cudaTriggerProgrammaticLaunchCompletion();
    __shared__ float sm[128 * 49];
    const int b = blockIdx.x;
    const int tid = threadIdx.x;

    if (b < PB_W1) {
        transpose_tile<49>(w1, g_w1T, W1N, b * 128, sm);
    } else if (b < PB_W1 + PB_W2) {
        transpose_tile<25>(w2, g_wT + WT2, 4096, (b - PB_W1) * 128, sm);
    } else if (b < PB_W1 + PB_W2 + PB_W3) {
        transpose_tile<25>(w3, g_wT + WT3, 4096, (b - PB_W1 - PB_W2) * 128, sm);
    } else if (b < PB_W1 + PB_W2 + PB_W3 + PB_SC) {
        int i = WT4 + (b - PB_W1 - PB_W2 - PB_W3) * 256 + tid;
        if (i < WT_TOTAL) {
            const float* src;
            int off, NPOS;
            if (i < WT5)      { src = w4; off = i - WT4; NPOS = 1024; }
            else if (i < WT6) { src = w5; off = i - WT5; NPOS = 1024; }
            else              { src = w6; off = i - WT6; NPOS = 256;  }
            int t, p;
            if (off < NPOS * 8) {
                int g = off / (4 * NPOS);
                int r = off % (4 * NPOS);
                p = r >> 2;
                t = 4 * g + (r & 3);
            } else {
                p = off - NPOS * 8;
                t = 8;
            }
            g_wT[i] = src[p * 9 + t];
        }
    } else {
        int i2 = (b - PB_W1 - PB_W2 - PB_W3 - PB_SC) * 256 + tid;
        float v = fcw[i2];
        if (__float_as_uint(v) == 0x7f800001u) g_sink = v;
    }
}

// =====================================================================
// Kernel A: L1 LC 7x7 -> relu -> g_t1. grid (32,16): 4 samples/block.
// PDL consumer: stage sample-0 patch (x only) before waiting on prep.
// =====================================================================
__global__ __launch_bounds__(256, 2) void l1_kernel(
    const float* __restrict__ x, const float* __restrict__ bias,
    float* __restrict__ out)
{
    __shared__ float xs[38 * 23];

    const int tid = threadIdx.x;
    const int bi = blockIdx.x >> 3;
    const int bj = blockIdx.x & 7;
    const int s0 = blockIdx.y * 4;
    const int oi = tid >> 3;
    const int oj2 = (tid & 7) * 2;
    const int gi = bi * 32 + oi;
    const int gj = bj * 16 + oj2;
    const int p0 = gi * 128 + gj;

    // ---- prologue: stage sample s0 patch (independent of prep) ----
    for (int idx = tid; idx < 38 * 22; idx += 256) {
        int pr = idx / 22, pc = idx % 22;
        int r = bi * 32 + pr - 3, c = bj * 16 + pc - 3;
        float v = 0.f;
        if (r >= 0 && r < 128 && c >= 0 && c < 128)
            v = x[(s0 * 128 + r) * 128 + c];
        xs[pr * 23 + pc] = v;
    }

    cudaGridDependencySynchronize();             // prep's w1T now valid

    float w0[49], w1r[49];
    const float4* A = (const float4*)g_w1T;
#pragma unroll
    for (int g = 0; g < 12; g++) {
        float4 a0 = A[g * W1N + p0];
        float4 a1 = A[g * W1N + p0 + 1];
        w0[4 * g] = a0.x; w0[4 * g + 1] = a0.y; w0[4 * g + 2] = a0.z; w0[4 * g + 3] = a0.w;
        w1r[4 * g] = a1.x; w1r[4 * g + 1] = a1.y; w1r[4 * g + 2] = a1.z; w1r[4 * g + 3] = a1.w;
    }
    w0[48] = g_w1T[48 * W1N + p0];
    w1r[48] = g_w1T[48 * W1N + p0 + 1];
    const float b0 = bias[p0], b1 = bias[p0 + 1];
    __syncthreads();                             // xs staging complete

    for (int sl = 0; sl < 4; sl++) {
        float acc0 = b0, acc1 = b1;
#pragma unroll
        for (int r = 0; r < 7; r++) {
            float xv[8];
#pragma unroll
            for (int c = 0; c < 8; c++) xv[c] = xs[(oi + r) * 23 + oj2 + c];
#pragma unroll
            for (int c = 0; c < 7; c++) {
                acc0 = fmaf(xv[c], w0[r * 7 + c], acc0);
                acc1 = fmaf(xv[c + 1], w1r[r * 7 + c], acc1);
            }
        }
        const int s = s0 + sl;
        float* o = &out[(s * 128 + gi) * 128 + gj];
        o[0] = fmaxf(acc0, 0.f);
        o[1] = fmaxf(acc1, 0.f);

        if (sl < 3) {
            __syncthreads();
            const int sn = s + 1;
            for (int idx = tid; idx < 38 * 22; idx += 256) {
                int pr = idx / 22, pc = idx % 22;
                int r = bi * 32 + pr - 3, c = bj * 16 + pc - 3;
                float v = 0.f;
                if (r >= 0 && r < 128 && c >= 0 && c < 128)
                    v = x[(sn * 128 + r) * 128 + c];
                xs[pr * 23 + pc] = v;
            }
            __syncthreads();
        }
    }
}

// =====================================================================
// Kernel B: fused L2..L6 (no PDL). L2/L3 lc_split now processes both
// outputs per thread with per-g weight loads (dual chains, no spill).
// =====================================================================
__device__ __forceinline__ void stats2(
    cg::cluster_group& cluster, float ls, float lq, float invn,
    float* RED, float* EXs, const float* peerEXs)
{
#pragma unroll
    for (int o = 16; o > 0; o >>= 1) {
        ls += __shfl_xor_sync(0xffffffffu, ls, o);
        lq += __shfl_xor_sync(0xffffffffu, lq, o);
    }
    const int wid = threadIdx.x >> 5, lane = threadIdx.x & 31;
    if (lane == 0) { RED[wid] = ls; RED[32 + wid] = lq; }
    __syncthreads();
    if (wid == 0) {
        float s = RED[lane], q = RED[32 + lane];
#pragma unroll
        for (int o = 16; o > 0; o >>= 1) {
            s += __shfl_xor_sync(0xffffffffu, s, o);
            q += __shfl_xor_sync(0xffffffffu, q, o);
        }
        if (lane == 0) { EXs[0] = s; EXs[1] = q; }
    }
    cluster.sync();
    if (threadIdx.x == 0) {
        float s = EXs[0] + peerEXs[0];
        float q = EXs[1] + peerEXs[1];
        float mu = s * invn;
        float var = q * invn - mu * mu;
        RED[64] = mu;
        RED[65] = rsqrtf(var + 1e-5f);
    }
    __syncthreads();
}

__device__ __forceinline__ void statsL(float ls, float lq, float invn, float* RED)
{
#pragma unroll
    for (int o = 16; o > 0; o >>= 1) {
        ls += __shfl_xor_sync(0xffffffffu, ls, o);
        lq += __shfl_xor_sync(0xffffffffu, lq, o);
    }
    const int wid = threadIdx.x >> 5, lane = threadIdx.x & 31;
    if (lane == 0) { RED[wid] = ls; RED[32 + wid] = lq; }
    __syncthreads();
    if (wid == 0) {
        float s = RED[lane], q = RED[32 + lane];
#pragma unroll
        for (int o = 16; o > 0; o >>= 1) {
            s += __shfl_xor_sync(0xffffffffu, s, o);
            q += __shfl_xor_sync(0xffffffffu, q, o);
        }
        if (lane == 0) {
            float mu = s * invn;
            float var = q * invn - mu * mu;
            RED[64] = mu;
            RED[65] = rsqrtf(var + 1e-5f);
        }
    }
    __syncthreads();
}

// L2/L3: both outputs per thread, per-g weight loads (8 live weight regs).
template <int HO, int KK, int STRIDE>
__device__ __forceinline__ void lc_split(
    const float* IN, float* OUT, const float* __restrict__ wT,
    const float* __restrict__ bias, int own0, float& ls, float& lq)
{
    constexpr int NPOS = HO * HO;
    constexpr int KB = KK * KK;
    constexpr int G = KB / 4;
    const float4* A = (const float4*)wT;

    const int p = threadIdx.x;
    const int q = p + 1024;
    const int li0 = p / HO, j0 = p % HO;
    const int li1 = q / HO, j1 = q % HO;
    const int gp = (own0 + li0) * HO + j0;
    const int gq = (own0 + li1) * HO + j1;
    const float* in0 = IN + li0 * STRIDE + j0;
    const float* in1 = IN + li1 * STRIDE + j1;
    float a0 = bias[gp], a1 = bias[gq];
#pragma unroll
    for (int g = 0; g < G; g++) {
        float4 wv0 = A[g * NPOS + gp];
        float4 wv1 = A[g * NPOS + gq];
#pragma unroll
        for (int jj = 0; jj < 4; jj++) {
            const int t = 4 * g + jj;
            const int r = t / KK, c = t % KK;
            const float wa = (jj == 0) ? wv0.x : (jj == 1) ? wv0.y
                           : (jj == 2) ? wv0.z : wv0.w;
            const float wb = (jj == 0) ? wv1.x : (jj == 1) ? wv1.y
                           : (jj == 2) ? wv1.z : wv1.w;
            a0 = fmaf(in0[r * STRIDE + c], wa, a0);
            a1 = fmaf(in1[r * STRIDE + c], wb, a1);
        }
    }
    {
        constexpr int t = KB - 1;
        constexpr int r = t / KK, c = t % KK;
        a0 = fmaf(in0[r * STRIDE + c], wT[4 * G * NPOS + gp], a0);
        a1 = fmaf(in1[r * STRIDE + c], wT[4 * G * NPOS + gq], a1);
    }
    a0 = fmaxf(a0, 0.f);
    a1 = fmaxf(a1, 0.f);
    OUT[p] = a0;
    OUT[q] = a1;
    ls += a0 + a1;
    lq += a0 * a0 + a1 * a1;
}

template <int HO, int KK, int STRIDE>
__device__ __forceinline__ void lc_full(
    const float* IN, float* OUT, const float* __restrict__ wT,
    const float* __restrict__ bias, float& ls, float& lq)
{
    constexpr int NPOS = HO * HO;
    constexpr int KB = KK * KK;
    constexpr int G = KB / 4;
    const float4* A = (const float4*)wT;
    int p = threadIdx.x;
    if (p < NPOS) {
        int oi = p / HO, oj = p % HO;
        const float* inb = IN + oi * STRIDE + oj;
        float acc = bias[p];
#pragma unroll
        for (int g = 0; g < G; g++) {
            float4 wv = A[g * NPOS + p];
#pragma unroll
            for (int jj = 0; jj < 4; jj++) {
                int t = 4 * g + jj;
                int r = t / KK, c = t % KK;
                float wj = (jj == 0) ? wv.x : (jj == 1) ? wv.y : (jj == 2) ? wv.z : wv.w;
                acc = fmaf(inb[r * STRIDE + c], wj, acc);
            }
        }
        {
            constexpr int t = KB - 1;
            constexpr int r = t / KK, c = t % KK;
            acc = fmaf(inb[r * STRIDE + c], wT[4 * G * NPOS + p], acc);
        }
        acc = fmaxf(acc, 0.f);
        OUT[p] = acc;
        ls += acc;
        lq += acc * acc;
    }
}

template <int ROWS, int HO, int PAD, int STRIDE>
__device__ __forceinline__ void zero_borders(float* IN)
{
    constexpr int BC = STRIDE - HO;
    for (int i = threadIdx.x; i < ROWS * BC; i += 1024) {
        int r = i / BC, c = i % BC;
        int col = (c < PAD) ? c : HO + c;
        IN[r * STRIDE + col] = 0.f;
    }
}

template <int HO, int PAD, int STRIDE>
__device__ __forceinline__ void ln_apply_split(
    const float* OUT, const float* peerOUT, float* IN,
    const float* __restrict__ g, const float* __restrict__ be,
    float mu, float rs, int h)
{
    constexpr int OH = HO / 2;
    constexpr int ROWS = OH + 2 * PAD;
    const int own0 = h * OH;
    zero_borders<ROWS, HO, PAD, STRIDE>(IN);
    for (int p = threadIdx.x; p < ROWS * HO; p += 1024) {
        int ri = p / HO, j = p % HO;
        int gr = own0 - PAD + ri;
        float val = 0.f;
        if (gr >= 0 && gr < HO) {
            bool own = (gr >= own0) && (gr < own0 + OH);
            const float* src = own ? OUT : peerOUT;
            int base = own ? own0 : (h ^ 1) * OH;
            float t = src[(gr - base) * HO + j];
            val = (t - mu) * rs * g[gr * HO + j] + be[gr * HO + j];
        }
        IN[ri * STRIDE + j + PAD] = val;
    }
}

template <int HO, int PAD, int STRIDE>   // HO = pooled size (32)
__device__ __forceinline__ void ln_pool_gather(
    const float* OUT, const float* peerOUT, float* IN,
    const float* __restrict__ g, const float* __restrict__ be,
    float mu, float rs, int h)
{
    constexpr int H2 = HO * 2;
    constexpr int ROWS = HO + 2 * PAD;
    zero_borders<ROWS, HO, PAD, STRIDE>(IN);
    for (int p = threadIdx.x; p < ROWS * HO; p += 1024) {
        int ri = p / HO, j = p % HO;
        int gr = ri - PAD;
        float val = 0.f;
        if (gr >= 0 && gr < HO) {
            int r2 = 2 * gr;
            bool own = (r2 >= h * HO) && (r2 < h * HO + HO);
            const float* src = own ? OUT : peerOUT;
            int base = own ? h * HO : (h ^ 1) * HO;
            float m = NEG_BIG;
#pragma unroll
            for (int dr = 0; dr < 2; dr++)
#pragma unroll
                for (int dc = 0; dc < 2; dc++) {
                    int grow = r2 + dr, gcol = 2 * j + dc;
                    int gi = grow * H2 + gcol;
                    float t = src[(grow - base) * H2 + gcol];
                    m = fmaxf(m, (t - mu) * rs * g[gi] + be[gi]);
                }
            val = m;
        }
        IN[ri * STRIDE + j + PAD] = val;
    }
}

template <int HO, int PAD, int STRIDE>
__device__ __forceinline__ void ln_apply_full(
    const float* OUT, float* IN, const float* __restrict__ g,
    const float* __restrict__ be, float mu, float rs)
{
    constexpr int ROWS = HO + 2 * PAD;
    zero_borders<ROWS, HO, PAD, STRIDE>(IN);
    for (int p = threadIdx.x; p < ROWS * HO; p += 1024) {
        int ri = p / HO, j = p % HO;
        int gr = ri - PAD;
        float val = 0.f;
        if (gr >= 0 && gr < HO) {
            float t = OUT[gr * HO + j];
            val = (t - mu) * rs * g[gr * HO + j] + be[gr * HO + j];
        }
        IN[ri * STRIDE + j + PAD] = val;
    }
}

template <int HO, int PAD, int STRIDE>   // HO = pooled size (16)
__device__ __forceinline__ void ln_pool_full(
    const float* OUT, float* IN, const float* __restrict__ g,
    const float* __restrict__ be, float mu, float rs)
{
    constexpr int H2 = HO * 2;
    constexpr int ROWS = HO + 2 * PAD;
    zero_borders<ROWS, HO, PAD, STRIDE>(IN);
    for (int p = threadIdx.x; p < ROWS * HO; p += 1024) {
        int ri = p / HO, j = p % HO;
        int gr = ri - PAD;
        float val = 0.f;
        if (gr >= 0 && gr < HO) {
            float m = NEG_BIG;
#pragma unroll
            for (int dr = 0; dr < 2; dr++)
#pragma unroll
                for (int dc = 0; dc < 2; dc++) {
                    int gi = (2 * gr + dr) * H2 + 2 * j + dc;
                    float t = OUT[gi];
                    m = fmaxf(m, (t - mu) * rs * g[gi] + be[gi]);
                }
            val = m;
        }
        IN[ri * STRIDE + j + PAD] = val;
    }
}

__global__ __launch_bounds__(1024) __cluster_dims__(2, 1, 1)
void fused_kernel(
    const float* __restrict__ b2, const float* __restrict__ b3,
    const float* __restrict__ b4, const float* __restrict__ b5,
    const float* __restrict__ b6,
    const float* __restrict__ g1, const float* __restrict__ be1,
    const float* __restrict__ g2, const float* __restrict__ be2,
    const float* __restrict__ g3, const float* __restrict__ be3,
    const float* __restrict__ g4, const float* __restrict__ be4,
    const float* __restrict__ g5, const float* __restrict__ be5,
    const float* __restrict__ g6, const float* __restrict__ be6)
{
    __shared__ __align__(16) float IN[36 * 68];
    __shared__ __align__(16) float OUTbuf[2][32 * 64];
    __shared__ __align__(16) float RED[66];
    __shared__ __align__(16) float EX[4];

    cg::cluster_group cluster = cg::this_cluster();
    const int h = (int)cluster.block_rank();
    const int s = blockIdx.x >> 1;
    const int tid = threadIdx.x;
    float* peerOUT0 = cluster.map_shared_rank(OUTbuf[0], h ^ 1);
    float* peerOUT1 = cluster.map_shared_rank(OUTbuf[1], h ^ 1);
    float* peerEXb = cluster.map_shared_rank(EX, h ^ 1);
    const float* t1s = g_t1 + s * 16384;

    // ---- LN1 stats over own half of t1 ----
    float ls = 0.f, lq = 0.f;
    {
        const float4* t4 = (const float4*)(t1s + h * 8192);
        for (int i = tid; i < 2048; i += 1024) {
            float4 v = t4[i];
            ls += v.x + v.y + v.z + v.w;
            lq += v.x * v.x + v.y * v.y + v.z * v.z + v.w * v.w;
        }
    }
    stats2(cluster, ls, lq, 1.f / 16384.f, RED, EX + 0, peerEXb + 0);
    float mu = RED[64], rs = RED[65];

    // ---- fill IN for L2 from global t1 (own 32 rows + 2 halo) ----
    zero_borders<36, 64, 2, 68>(IN);
    for (int p = tid; p < 36 * 64; p += 1024) {
        int ri = p >> 6, j = p & 63;
        int gr = h * 32 - 2 + ri;
        float val = 0.f;
        if (gr >= 0 && gr < 64) {
            float m = NEG_BIG;
#pragma unroll
            for (int dr = 0; dr < 2; dr++)
#pragma unroll
                for (int dc = 0; dc < 2; dc++) {
                    int gi = (2 * gr + dr) * 128 + 2 * j + dc;
                    float t = t1s[gi];
                    m = fmaxf(m, (t - mu) * rs * g1[gi] + be1[gi]);
                }
            val = m;
        }
        IN[ri * 68 + j + 2] = val;
    }
    __syncthreads();

    // ---- L2 split (OUT buf 0, EX slot 1) ----
    ls = lq = 0.f;
    lc_split<64, 5, 68>(IN, OUTbuf[0], g_wT + WT2, b2, h * 32, ls, lq);
    stats2(cluster, ls, lq, 1.f / 4096.f, RED, EX + 2, peerEXb + 2);
    mu = RED[64]; rs = RED[65];
    ln_apply_split<64, 2, 68>(OUTbuf[0], peerOUT0, IN, g2, be2, mu, rs, h);
    __syncthreads();

    // ---- L3 split (OUT buf 1, EX slot 0) ----
    ls = lq = 0.f;
    lc_split<64, 5, 68>(IN, OUTbuf[1], g_wT + WT3, b3, h * 32, ls, lq);
    stats2(cluster, ls, lq, 1.f / 4096.f, RED, EX + 0, peerEXb + 0);
    mu = RED[64]; rs = RED[65];
    ln_pool_gather<32, 1, 34>(OUTbuf[1], peerOUT1, IN, g3, be3, mu, rs, h);
    cluster.sync();    // last peer-SMEM interaction

    // ======== fully local, redundant on both CTAs ========

    // ---- L4 full ----
    ls = lq = 0.f;
    lc_full<32, 3, 34>(IN, OUTbuf[0], g_wT + WT4, b4, ls, lq);
    statsL(ls, lq, 1.f / 1024.f, RED);
    mu = RED[64]; rs = RED[65];
    ln_apply_full<32, 1, 34>(OUTbuf[0], IN, g4, be4, mu, rs);
    __syncthreads();

    // ---- L5 full ----
    ls = lq = 0.f;
    lc_full<32, 3, 34>(IN, OUTbuf[1], g_wT + WT5, b5, ls, lq);
    statsL(ls, lq, 1.f / 1024.f, RED);
    mu = RED[64]; rs = RED[65];
    ln_pool_full<16, 1, 18>(OUTbuf[1], IN, g5, be5, mu, rs);
    __syncthreads();

    // ---- L6 full ----
    ls = lq = 0.f;
    lc_full<16, 3, 18>(IN, OUTbuf[0], g_wT + WT6, b6, ls, lq);
    statsL(ls, lq, 1.f / 256.f, RED);
    mu = RED[64]; rs = RED[65];
    if (tid < 128) {
        int gp = h * 128 + tid;
        g_t6[s * 256 + gp] = (OUTbuf[0][gp] - mu) * rs * g6[gp] + be6[gp];
    }
}

// =====================================================================
// Kernel C: FC GEMM partials, k-split 4. PDL consumer (Ws overlap).
// =====================================================================
__global__ __launch_bounds__(256) void fc_kernel(const float* __restrict__ fcw)
{
    __shared__ float Ws[64 * 34];
    __shared__ float Xs[64 * 34];

    const int tid = threadIdx.x;
    const int o0 = blockIdx.x * 32;
    const int s0 = blockIdx.y * 32;
    const int k0 = blockIdx.z * 64;

    cudaTriggerProgrammaticLaunchCompletion();   // let softmax begin

    for (int idx = tid; idx < 32 * 64; idx += 256) {
        int o = idx >> 6, k = idx & 63;
        Ws[k * 34 + o] = fcw[(o0 + o) * 256 + k0 + k];
    }

    cudaGridDependencySynchronize();             // fused's g_t6 now valid

    for (int idx = tid; idx < 32 * 64; idx += 256) {
        int ss = idx >> 6, k = idx & 63;
        Xs[k * 34 + ss] = g_t6[(s0 + ss) * 256 + k0 + k];
    }
    __syncthreads();

    const int oL = (tid & 15) * 2;
    const int sL = (tid >> 4) * 2;
    float a00 = 0.f, a01 = 0.f, a10 = 0.f, a11 = 0.f;
#pragma unroll 8
    for (int k = 0; k < 64; k++) {
        float2 wv = *(const float2*)&Ws[k * 34 + oL];
        float2 xv = *(const float2*)&Xs[k * 34 + sL];
        a00 = fmaf(wv.x, xv.x, a00);
        a10 = fmaf(wv.y, xv.x, a10);
        a01 = fmaf(wv.x, xv.y, a01);
        a11 = fmaf(wv.y, xv.y, a11);
    }
    float* dst = g_fcp[blockIdx.z];
    dst[(s0 + sL) * 1024 + o0 + oL] = a00;
    dst[(s0 + sL) * 1024 + o0 + oL + 1] = a10;
    dst[(s0 + sL + 1) * 1024 + o0 + oL] = a01;
    dst[(s0 + sL + 1) * 1024 + o0 + oL + 1] = a11;
}

// =====================================================================
// Kernel D: combine 4 FC partials + bias, softmax. PDL consumer.
// =====================================================================
__global__ __launch_bounds__(256) void softmax_kernel(
    const float* __restrict__ fcb, float* __restrict__ out)
{
    __shared__ float red1[8];
    __shared__ float red2[8];
    const int s = blockIdx.x, tid = threadIdx.x;
    const int wid = tid >> 5, lane = tid & 31;

    const float4* pb = (const float4*)fcb;
    float4 e = pb[tid];                          // independent of fc

    cudaGridDependencySynchronize();             // fc's partials now valid

    const float4* p0 = (const float4*)&g_fcp[0][s * 1024];
    const float4* p1 = (const float4*)&g_fcp[1][s * 1024];
    const float4* p2 = (const float4*)&g_fcp[2][s * 1024];
    const float4* p3 = (const float4*)&g_fcp[3][s * 1024];
    float4 a = p0[tid], b = p1[tid], c = p2[tid], d = p3[tid];
    float4 v;
    v.x = a.x + b.x + c.x + d.x + e.x;
    v.y = a.y + b.y + c.y + d.y + e.y;
    v.z = a.z + b.z + c.z + d.z + e.z;
    v.w = a.w + b.w + c.w + d.w + e.w;

    float m = fmaxf(fmaxf(v.x, v.y), fmaxf(v.z, v.w));
#pragma unroll
    for (int o = 16; o > 0; o >>= 1) m = fmaxf(m, __shfl_xor_sync(0xffffffffu, m, o));
    if (lane == 0) red1[wid] = m;
    __syncthreads();
    m = red1[0];
#pragma unroll
    for (int i = 1; i < 8; i++) m = fmaxf(m, red1[i]);

    v.x = __expf(v.x - m);
    v.y = __expf(v.y - m);
    v.z = __expf(v.z - m);
    v.w = __expf(v.w - m);
    float sum = v.x + v.y + v.z + v.w;
#pragma unroll
    for (int o = 16; o > 0; o >>= 1) sum += __shfl_xor_sync(0xffffffffu, sum, o);
    if (lane == 0) red2[wid] = sum;
    __syncthreads();
    float tot = 0.f;
#pragma unroll
    for (int i = 0; i < 8; i++) tot += red2[i];
    const float inv = 1.f / tot;

    float4 r;
    r.x = v.x * inv; r.y = v.y * inv; r.z = v.z * inv; r.w = v.w * inv;
    ((float4*)&out[s * 1024])[tid] = r;
}

// ---------------- launch ----------------
extern "C" void kernel_launch(void* const* d_in, const int* in_sizes, int n_in,
                              void* d_out, int out_size)
{
    const float* X = (const float*)d_in[0];
    const float* W[6];
    const float* Bi[6];
    const float* G[6];
    const float* Be[6];
    for (int i = 0; i < 6; i++) {
        W[i]  = (const float*)d_in[1 + 4 * i];
        Bi[i] = (const float*)d_in[2 + 4 * i];
        G[i]  = (const float*)d_in[3 + 4 * i];
        Be[i] = (const float*)d_in[4 + 4 * i];
    }
    const float* FCW = (const float*)d_in[25];
    const float* FCB = (const float*)d_in[26];

    float* t1;
    cudaGetSymbolAddress((void**)&t1, g_t1);

    cudaLaunchAttribute pdl[1];
    pdl[0].id = cudaLaunchAttributeProgrammaticStreamSerialization;
    pdl[0].val.programmaticStreamSerializationAllowed = 1;

    prep_kernel<<<PB_TOTAL, 256>>>(
        W[0], W[1], W[2], W[3], W[4], W[5], FCW);

    {   // small consumer: co-resides with prep, useful prologue
        cudaLaunchConfig_t cfg = {};
        cfg.gridDim = dim3(32, 16); cfg.blockDim = dim3(256);
        cfg.stream = 0; cfg.attrs = pdl; cfg.numAttrs = 1;
        cudaLaunchKernelEx(&cfg, l1_kernel, X, Bi[0], (float*)t1);
    }

    // fused: plain launch (32-warp CTAs would displace l1 if PDL'd)
    fused_kernel<<<128, 1024>>>(
        Bi[1], Bi[2], Bi[3], Bi[4], Bi[5],
        G[0], Be[0], G[1], Be[1], G[2], Be[2],
        G[3], Be[3], G[4], Be[4], G[5], Be[5]);

    {
        cudaLaunchConfig_t cfg = {};
        cfg.gridDim = dim3(32, 2, 4); cfg.blockDim = dim3(256);
        cfg.stream = 0; cfg.attrs = pdl; cfg.numAttrs = 1;
        cudaLaunchKernelEx(&cfg, fc_kernel, FCW);
    }
    {
        cudaLaunchConfig_t cfg = {};
        cfg.gridDim = dim3(64); cfg.blockDim = dim3(256);
        cfg.stream = 0; cfg.attrs = pdl; cfg.numAttrs = 1;
        cudaLaunchKernelEx(&cfg, softmax_kernel, FCB, (float*)d_out);
    }
}